// round 8
// baseline (speedup 1.0000x reference)
#include <cuda_runtime.h>
#include <cuda_fp16.h>
#include <cstring>

#define NN 100000
#define EE 400000
#define D4 64          // 256 floats = 64 float4 per row
#define SS 10000
#define CAP 64         // bucket capacity per node (Poisson(8): P(>64) ~ 0)

// ---------------- static scratch (no runtime allocation) ----------------
// g_cursor is zero-initialized at module load and re-zeroed at the END of
// each kernel_launch (in k_seed), so every call starts from zeros.
__device__ int    g_cursor[2][NN];            // degree counts (bucket cursors)
__device__ int    g_adj[2][(size_t)NN * CAP]; // bucket adjacency
__device__ float  g_dinv[2][NN];
__device__ uint4  g_h0[2][(size_t)NN * 32];   // fp16 pre-scaled g0 = h*dinv (512B/row)
__device__ uint4  g_h1[2][(size_t)NN * 32];   // fp16 pre-scaled g1

// ---------------- half2 <-> float helpers ----------------
__device__ __forceinline__ float2 u2f(unsigned int u) {
    __half2 h; memcpy(&h, &u, 4); return __half22float2(h);
}
__device__ __forceinline__ unsigned int f2u(float a, float b) {
    __half2 h = __floats2half2_rn(a, b); unsigned int u; memcpy(&u, &h, 4); return u;
}
__device__ __forceinline__ void unpack_add8(float* a, uint4 v) {
    float2 f;
    f = u2f(v.x); a[0] += f.x; a[1] += f.y;
    f = u2f(v.y); a[2] += f.x; a[3] += f.y;
    f = u2f(v.z); a[4] += f.x; a[5] += f.y;
    f = u2f(v.w); a[6] += f.x; a[7] += f.y;
}

// ---------------- bucket fill: one pass builds adjacency AND degrees ------
__global__ void k_fill(const int2* __restrict__ esr, const int2* __restrict__ etg) {
    int i = blockIdx.x * 256 + threadIdx.x;
    if (i >= 2 * EE) return;
    int side = i >= EE;
    int j = i - side * EE;
    int2 ab = side ? etg[j] : esr[j];
    int p = atomicAdd(&g_cursor[side][ab.x], 1);
    if (p < CAP) g_adj[side][(size_t)ab.x * CAP + p] = ab.y;
    int q = atomicAdd(&g_cursor[side][ab.y], 1);
    if (q < CAP) g_adj[side][(size_t)ab.y * CAP + q] = ab.x;
}

// dinv[v] = rsqrt(deg[v] + 1)   (cursor count == degree)
__global__ void k_dinv() {
    int i = blockIdx.x * 256 + threadIdx.x;
    if (i >= 2 * NN) return;
    int side = i >= NN;
    int v = i - side * NN;
    g_dinv[side][v] = rsqrtf((float)(g_cursor[side][v] + 1));
}

// g0 = fp16(feats * dinv[row]); one uint4 (8 halfs) per thread
__global__ void k_conv(const float4* __restrict__ fsr, const float4* __restrict__ ftg) {
    int i = blockIdx.x * 256 + threadIdx.x;
    if (i >= 2 * NN * 32) return;
    int side = i >= NN * 32;
    int j = i - side * NN * 32;
    float s = g_dinv[side][j >> 5];
    const float4* f = side ? ftg : fsr;
    float4 x0 = __ldcs(f + 2 * j);        // streaming: feats never reused
    float4 x1 = __ldcs(f + 2 * j + 1);
    uint4 o;
    o.x = f2u(x0.x * s, x0.y * s);
    o.y = f2u(x0.z * s, x0.w * s);
    o.z = f2u(x1.x * s, x1.y * s);
    o.w = f2u(x1.z * s, x1.w * s);
    g_h0[side][j] = o;
}

// ---------------- aggregation: one warp per node, 8 floats / lane --------
// lane l holds float columns [8l .. 8l+7]  (one uint4 = 8 halfs per row)
// Input table is pre-scaled by dinv -> inner loop is a pure gather-add.
// Latency fix: unroll-by-4 batched INDEPENDENT loads (MLP 1 -> 4).
// FINAL=false: g1[v] = fp16( relu(dinv[v]*acc) * dinv[v] )  -> g_h1
// FINAL=true : row    = l2normalize(dinv[v]*acc)            -> d_out (fp32, stcs)
template <bool FINAL>
__global__ void __launch_bounds__(256, 5) k_layer(int side, float4* out) {
    int gw = (blockIdx.x * blockDim.x + threadIdx.x) >> 5;
    if (gw >= NN) return;
    int lane = threadIdx.x & 31;

    const uint4* __restrict__ gin = FINAL ? g_h1[side] : g_h0[side];
    float a[8] = {0, 0, 0, 0, 0, 0, 0, 0};

    int e = min(g_cursor[side][gw], CAP);
    const int* __restrict__ adj = g_adj[side] + (size_t)gw * CAP;

    // self-loop row load issued first (independent of neighbor loads)
    uint4 vself = __ldg(gin + (size_t)gw * 32 + lane);

    for (int base = 0; base < e; base += 32) {
        int cnt = min(32, e - base);
        int nb = (lane < cnt) ? __ldg(adj + base + lane) : 0;
        int k = 0;
        for (; k + 4 <= cnt; k += 4) {
            int u0 = __shfl_sync(0xffffffffu, nb, k);
            int u1 = __shfl_sync(0xffffffffu, nb, k + 1);
            int u2 = __shfl_sync(0xffffffffu, nb, k + 2);
            int u3 = __shfl_sync(0xffffffffu, nb, k + 3);
            uint4 v0 = __ldg(gin + (size_t)u0 * 32 + lane);   // 4 independent
            uint4 v1 = __ldg(gin + (size_t)u1 * 32 + lane);   // LDG.128s in
            uint4 v2 = __ldg(gin + (size_t)u2 * 32 + lane);   // flight together
            uint4 v3 = __ldg(gin + (size_t)u3 * 32 + lane);
            unpack_add8(a, v0);
            unpack_add8(a, v1);
            unpack_add8(a, v2);
            unpack_add8(a, v3);
        }
        if (k < cnt) {
            uint4 w0, w1, w2;
            int rem = cnt - k;
            int u0 = __shfl_sync(0xffffffffu, nb, k);
            w0 = __ldg(gin + (size_t)u0 * 32 + lane);
            if (rem > 1) { int u1 = __shfl_sync(0xffffffffu, nb, k + 1);
                           w1 = __ldg(gin + (size_t)u1 * 32 + lane); }
            if (rem > 2) { int u2 = __shfl_sync(0xffffffffu, nb, k + 2);
                           w2 = __ldg(gin + (size_t)u2 * 32 + lane); }
            unpack_add8(a, w0);
            if (rem > 1) unpack_add8(a, w1);
            if (rem > 2) unpack_add8(a, w2);
        }
    }
    unpack_add8(a, vself);

    float dv = g_dinv[side][gw];
    if (!FINAL) {
        float r[8];
        #pragma unroll
        for (int k = 0; k < 8; k++) r[k] = fmaxf(dv * a[k], 0.f) * dv;
        uint4 o;
        o.x = f2u(r[0], r[1]); o.y = f2u(r[2], r[3]);
        o.z = f2u(r[4], r[5]); o.w = f2u(r[6], r[7]);
        g_h1[side][(size_t)gw * 32 + lane] = o;
    } else {
        float r[8];
        float ss = 0.f;
        #pragma unroll
        for (int k = 0; k < 8; k++) { r[k] = dv * a[k]; ss += r[k] * r[k]; }
        #pragma unroll
        for (int off = 16; off; off >>= 1) ss += __shfl_xor_sync(0xffffffffu, ss, off);
        float inv = 1.0f / fmaxf(sqrtf(ss), 1e-12f);
        float4 r0, r1;
        r0.x = r[0] * inv; r0.y = r[1] * inv; r0.z = r[2] * inv; r0.w = r[3] * inv;
        r1.x = r[4] * inv; r1.y = r[5] * inv; r1.z = r[6] * inv; r1.w = r[7] * inv;
        size_t rb = (size_t)(2 * SS) * D4 + (size_t)side * NN * D4 + (size_t)gw * D4;
        __stcs(out + rb + 2 * lane, r0);       // streaming: keep gather table in L2
        __stcs(out + rb + 2 * lane + 1, r1);
    }
}

// seed gather + re-zero bucket cursors for the next call
__global__ void k_seed(const int* __restrict__ ssr, const int* __restrict__ stg,
                       float4* out) {
    int i = blockIdx.x * 256 + threadIdx.x;
    if (i < 2 * NN) ((int*)g_cursor)[i] = 0;
    if (i >= 2 * SS * D4) return;
    int row = i >> 6, c = i & 63;
    int side = row >= SS;
    int s = row - side * SS;
    int node = side ? stg[s] : ssr[s];
    size_t src = (size_t)(2 * SS) * D4 + (size_t)side * NN * D4 + (size_t)node * D4 + c;
    out[i] = out[src];
}

// ---------------- launch ----------------
extern "C" void kernel_launch(void* const* d_in, const int* in_sizes, int n_in,
                              void* d_out, int out_size) {
    const float4* fsr = (const float4*)d_in[0];
    const float4* ftg = (const float4*)d_in[1];
    const int2*   esr = (const int2*)d_in[2];
    const int2*   etg = (const int2*)d_in[3];
    const int*    ssr = (const int*)d_in[4];
    const int*    stg = (const int*)d_in[5];
    float4* out = (float4*)d_out;

    k_fill<<<(2 * EE + 255) / 256, 256>>>(esr, etg);
    k_dinv<<<(2 * NN + 255) / 256, 256>>>();
    k_conv<<<(2 * NN * 32 + 255) / 256, 256>>>(fsr, ftg);

    // per-side chain: layer-2 consumes g_h1 while it is still L2-resident;
    // sides sequential keeps the working set under the 126 MB L2
    int lb = (NN * 32 + 255) / 256;   // one warp per node
    k_layer<false><<<lb, 256>>>(0, nullptr);
    k_layer<true ><<<lb, 256>>>(0, out);
    k_layer<false><<<lb, 256>>>(1, nullptr);
    k_layer<true ><<<lb, 256>>>(1, out);

    k_seed<<<(2 * SS * D4 + 255) / 256, 256>>>(ssr, stg, out);
}